// round 1
// baseline (speedup 1.0000x reference)
#include <cuda_runtime.h>
#include <math.h>

// Problem constants
#define BB 2
#define SS 2048
#define DD 1024
#define HH 16
#define HD 64
#define MM (BB * SS)   // 4096

// Scratch: head-layout Q,K,V,CTX  [B,H,S,HD] fp32 (16 MB each)
__device__ float g_q[BB * HH * SS * HD];
__device__ float g_k[BB * HH * SS * HD];
__device__ float g_v[BB * HH * SS * HD];
__device__ float g_ctx[BB * HH * SS * HD];

// ---------------------------------------------------------------------------
// Kernel 1: QKV projection.  C[m,n] = sum_k X[m,k] * W[n,k] + bias[n]
// Tile: BM=128, BN=64, BK=16; 256 threads, 8x4 per thread.
// Output written into head layout [B,H,S,HD].
// grid = (1024/64, 4096/128, 3)
// ---------------------------------------------------------------------------
__global__ __launch_bounds__(256, 2)
void qkv_proj_kernel(const float* __restrict__ q_in,
                     const float* __restrict__ k_in,
                     const float* __restrict__ v_in,
                     const float* __restrict__ Wq, const float* __restrict__ bq,
                     const float* __restrict__ Wk, const float* __restrict__ bk,
                     const float* __restrict__ Wv, const float* __restrict__ bv) {
    const int which = blockIdx.z;
    const float* __restrict__ X    = (which == 0) ? q_in : (which == 1) ? k_in : v_in;
    const float* __restrict__ W    = (which == 0) ? Wq   : (which == 1) ? Wk   : Wv;
    const float* __restrict__ bias = (which == 0) ? bq   : (which == 1) ? bk   : bv;
    float* __restrict__ out        = (which == 0) ? g_q  : (which == 1) ? g_k  : g_v;

    __shared__ float Xs[16][132];   // [k][m], padded
    __shared__ float Ws[16][68];    // [k][n], padded

    const int tid = threadIdx.x;
    const int m0 = blockIdx.y * 128;
    const int n0 = blockIdx.x * 64;
    const int tx = tid & 15;        // 16 col groups  (4 cols each)
    const int ty = tid >> 4;        // 16 row groups  (8 rows each)
    const int kk = tid & 15;        // load: k within tile
    const int rx = tid >> 4;        // load: base row

    float acc[8][4];
#pragma unroll
    for (int i = 0; i < 8; i++)
#pragma unroll
        for (int j = 0; j < 4; j++) acc[i][j] = 0.f;

    for (int k0 = 0; k0 < DD; k0 += 16) {
#pragma unroll
        for (int r = 0; r < 8; r++)
            Xs[kk][rx + r * 16] = X[(size_t)(m0 + rx + r * 16) * DD + k0 + kk];
#pragma unroll
        for (int r = 0; r < 4; r++)
            Ws[kk][rx + r * 16] = W[(size_t)(n0 + rx + r * 16) * DD + k0 + kk];
        __syncthreads();

#pragma unroll
        for (int k = 0; k < 16; k++) {
            float a[8], b[4];
#pragma unroll
            for (int i = 0; i < 8; i++) a[i] = Xs[k][ty * 8 + i];
#pragma unroll
            for (int j = 0; j < 4; j++) b[j] = Ws[k][tx * 4 + j];
#pragma unroll
            for (int i = 0; i < 8; i++)
#pragma unroll
                for (int j = 0; j < 4; j++) acc[i][j] = fmaf(a[i], b[j], acc[i][j]);
        }
        __syncthreads();
    }

    const int h = n0 >> 6;   // one head per 64-wide tile
#pragma unroll
    for (int i = 0; i < 8; i++) {
        const int m = m0 + ty * 8 + i;
        const int b = m >> 11;        // /2048
        const int s = m & 2047;
        float* orow = out + ((size_t)(b * HH + h) * SS + s) * HD;
#pragma unroll
        for (int j = 0; j < 4; j++) {
            const int n = n0 + tx * 4 + j;
            orow[tx * 4 + j] = acc[i][j] + bias[n];
        }
    }
}

// ---------------------------------------------------------------------------
// Kernel 2: causal flash attention per (q-tile=64, head, batch).
// 256 threads: tx = tid&15 (4 cols), ty = tid>>4 (4 rows).
// Dynamic smem: Qs,Ks,Vs,Ps each [64][65] floats.
// ---------------------------------------------------------------------------
#define FA_SMEM (4 * 64 * 65 * sizeof(float))

__global__ __launch_bounds__(256, 2)
void flash_attn_kernel() {
    extern __shared__ float smem[];
    float (*Qs)[65] = (float (*)[65])(smem);
    float (*Ks)[65] = (float (*)[65])(smem + 64 * 65);
    float (*Vs)[65] = (float (*)[65])(smem + 2 * 64 * 65);
    float (*Ps)[65] = (float (*)[65])(smem + 3 * 64 * 65);

    const int qt = blockIdx.x;
    const int h  = blockIdx.y;
    const int b  = blockIdx.z;
    const int tid = threadIdx.x;
    const int tx = tid & 15;
    const int ty = tid >> 4;
    const int q0 = qt * 64;

    const float* __restrict__ Qb = g_q + (size_t)(b * HH + h) * SS * HD;
    const float* __restrict__ Kb = g_k + (size_t)(b * HH + h) * SS * HD;
    const float* __restrict__ Vb = g_v + (size_t)(b * HH + h) * SS * HD;

    // load Q tile
    for (int i = tid; i < 64 * 64; i += 256) {
        const int r = i >> 6, c = i & 63;
        Qs[r][c] = Qb[(size_t)(q0 + r) * HD + c];
    }

    float acc[4][4];
    float mrow[4], lrow[4];
#pragma unroll
    for (int i = 0; i < 4; i++) {
        mrow[i] = -1e30f;
        lrow[i] = 0.f;
#pragma unroll
        for (int j = 0; j < 4; j++) acc[i][j] = 0.f;
    }

    const float scale = 0.125f;  // 1/sqrt(64)
    const int ntiles = qt + 1;   // causal

    for (int t = 0; t < ntiles; t++) {
        const int k0 = t * 64;
        for (int i = tid; i < 64 * 64; i += 256) {
            const int r = i >> 6, c = i & 63;
            Ks[r][c] = Kb[(size_t)(k0 + r) * HD + c];
            Vs[r][c] = Vb[(size_t)(k0 + r) * HD + c];
        }
        __syncthreads();

        // S = Q K^T (4x4 per thread)
        float sv[4][4];
#pragma unroll
        for (int i = 0; i < 4; i++)
#pragma unroll
            for (int j = 0; j < 4; j++) sv[i][j] = 0.f;

#pragma unroll 8
        for (int k = 0; k < 64; k++) {
            float a[4], bb[4];
#pragma unroll
            for (int i = 0; i < 4; i++) a[i]  = Qs[ty * 4 + i][k];
#pragma unroll
            for (int j = 0; j < 4; j++) bb[j] = Ks[tx * 4 + j][k];
#pragma unroll
            for (int i = 0; i < 4; i++)
#pragma unroll
                for (int j = 0; j < 4; j++) sv[i][j] = fmaf(a[i], bb[j], sv[i][j]);
        }

        // scale + causal mask (matches reference: scores*scale + (-1e9)*mask)
#pragma unroll
        for (int i = 0; i < 4; i++) {
            const int qi = q0 + ty * 4 + i;
#pragma unroll
            for (int j = 0; j < 4; j++) {
                const int kj = k0 + tx * 4 + j;
                float x = sv[i][j] * scale;
                if (kj > qi) x -= 1e9f;
                sv[i][j] = x;
            }
        }

        // online softmax: row max / sum across the 16 tx lanes (same half of warp)
        float mt[4], rs[4];
#pragma unroll
        for (int i = 0; i < 4; i++) {
            float m = fmaxf(fmaxf(sv[i][0], sv[i][1]), fmaxf(sv[i][2], sv[i][3]));
#pragma unroll
            for (int off = 8; off >= 1; off >>= 1)
                m = fmaxf(m, __shfl_xor_sync(0xffffffffu, m, off));
            mt[i] = m;
        }
#pragma unroll
        for (int i = 0; i < 4; i++) {
            const float mnew = fmaxf(mrow[i], mt[i]);
            const float alpha = __expf(mrow[i] - mnew);
            float s = 0.f;
#pragma unroll
            for (int j = 0; j < 4; j++) {
                const float p = __expf(sv[i][j] - mnew);
                sv[i][j] = p;
                s += p;
            }
#pragma unroll
            for (int off = 8; off >= 1; off >>= 1)
                s += __shfl_xor_sync(0xffffffffu, s, off);
            lrow[i] = lrow[i] * alpha + s;
            mrow[i] = mnew;
#pragma unroll
            for (int j = 0; j < 4; j++) acc[i][j] *= alpha;
        }

        // stage P
#pragma unroll
        for (int i = 0; i < 4; i++)
#pragma unroll
            for (int j = 0; j < 4; j++) Ps[ty * 4 + i][tx * 4 + j] = sv[i][j];
        __syncthreads();

        // O += P @ V
#pragma unroll 8
        for (int c = 0; c < 64; c++) {
            float pr[4], vv[4];
#pragma unroll
            for (int i = 0; i < 4; i++) pr[i] = Ps[ty * 4 + i][c];
#pragma unroll
            for (int j = 0; j < 4; j++) vv[j] = Vs[c][tx * 4 + j];
#pragma unroll
            for (int i = 0; i < 4; i++)
#pragma unroll
                for (int j = 0; j < 4; j++) acc[i][j] = fmaf(pr[i], vv[j], acc[i][j]);
        }
        __syncthreads();
    }

    // normalize + store ctx [B,H,S,HD]
#pragma unroll
    for (int i = 0; i < 4; i++) {
        const float inv = 1.0f / lrow[i];
        float* orow = g_ctx + ((size_t)(b * HH + h) * SS + q0 + ty * 4 + i) * HD;
#pragma unroll
        for (int j = 0; j < 4; j++) orow[tx * 4 + j] = acc[i][j] * inv;
    }
}

// ---------------------------------------------------------------------------
// Kernel 3: output projection.  out[m,n] = sum_k ctx[m,k] * Wo[n,k] + bo[n]
// ctx gathered from head layout.
// ---------------------------------------------------------------------------
__global__ __launch_bounds__(256, 2)
void out_proj_kernel(const float* __restrict__ Wo, const float* __restrict__ bo,
                     float* __restrict__ out) {
    __shared__ float Xs[16][132];
    __shared__ float Ws[16][68];

    const int tid = threadIdx.x;
    const int m0 = blockIdx.y * 128;
    const int n0 = blockIdx.x * 64;
    const int tx = tid & 15;
    const int ty = tid >> 4;
    const int kk = tid & 15;
    const int rx = tid >> 4;

    float acc[8][4];
#pragma unroll
    for (int i = 0; i < 8; i++)
#pragma unroll
        for (int j = 0; j < 4; j++) acc[i][j] = 0.f;

    for (int k0 = 0; k0 < DD; k0 += 16) {
        const int k = k0 + kk;
        const int kh = k >> 6;      // head
        const int kd = k & 63;      // dim within head
#pragma unroll
        for (int r = 0; r < 8; r++) {
            const int m = m0 + rx + r * 16;
            const int b = m >> 11;
            const int s = m & 2047;
            Xs[kk][rx + r * 16] = g_ctx[((size_t)(b * HH + kh) * SS + s) * HD + kd];
        }
#pragma unroll
        for (int r = 0; r < 4; r++)
            Ws[kk][rx + r * 16] = Wo[(size_t)(n0 + rx + r * 16) * DD + k0 + kk];
        __syncthreads();

#pragma unroll
        for (int kq = 0; kq < 16; kq++) {
            float a[8], b[4];
#pragma unroll
            for (int i = 0; i < 8; i++) a[i] = Xs[kq][ty * 8 + i];
#pragma unroll
            for (int j = 0; j < 4; j++) b[j] = Ws[kq][tx * 4 + j];
#pragma unroll
            for (int i = 0; i < 8; i++)
#pragma unroll
                for (int j = 0; j < 4; j++) acc[i][j] = fmaf(a[i], b[j], acc[i][j]);
        }
        __syncthreads();
    }

#pragma unroll
    for (int i = 0; i < 8; i++) {
        const int m = m0 + ty * 8 + i;
#pragma unroll
        for (int j = 0; j < 4; j++) {
            const int n = n0 + tx * 4 + j;
            out[(size_t)m * DD + n] = acc[i][j] + bo[n];
        }
    }
}

// ---------------------------------------------------------------------------
extern "C" void kernel_launch(void* const* d_in, const int* in_sizes, int n_in,
                              void* d_out, int out_size) {
    const float* query = (const float*)d_in[0];
    const float* key   = (const float*)d_in[1];
    const float* value = (const float*)d_in[2];
    // d_in[3] = mask (causal; applied analytically in-kernel)
    const float* Wq = (const float*)d_in[4];
    const float* bq = (const float*)d_in[5];
    const float* Wk = (const float*)d_in[6];
    const float* bk = (const float*)d_in[7];
    const float* Wv = (const float*)d_in[8];
    const float* bv = (const float*)d_in[9];
    const float* Wo = (const float*)d_in[10];
    const float* bo = (const float*)d_in[11];
    float* out = (float*)d_out;

    // idempotent; safe under graph capture (not a stream op)
    cudaFuncSetAttribute(flash_attn_kernel,
                         cudaFuncAttributeMaxDynamicSharedMemorySize, FA_SMEM);

    dim3 gproj(DD / 64, MM / 128, 3);
    qkv_proj_kernel<<<gproj, 256>>>(query, key, value, Wq, bq, Wk, bk, Wv, bv);

    dim3 gfa(SS / 64, HH, BB);
    flash_attn_kernel<<<gfa, 256, FA_SMEM>>>();

    dim3 gout(DD / 64, MM / 128);
    out_proj_kernel<<<gout, 256>>>(Wo, bo, out);
}

// round 2
// speedup vs baseline: 1.8208x; 1.8208x over previous
#include <cuda_runtime.h>
#include <math.h>
#include <stdint.h>

// Problem constants
#define BB 2
#define SS 2048
#define DD 1024
#define HH 16
#define HD 64
#define MM (BB * SS)   // 4096

// Scratch: Q,K,V in head layout [B,H,S,HD]; CTX in [B,S,D] (GEMM-friendly)
__device__ float g_q[BB * HH * SS * HD];
__device__ float g_k[BB * HH * SS * HD];
__device__ float g_v[BB * HH * SS * HD];
__device__ float g_ctx[BB * SS * DD];

// ---------------------------------------------------------------------------
// tf32 tensor-core GEMM machinery: C[m,n] = sum_k X[m,k] * W[n,k]
// Block tile 128x128, BK=32, 256 threads (8 warps, 2x4 warp grid, 64x32/warp).
// Register double-buffered global loads; explicit cvt.rna.tf32.
// ---------------------------------------------------------------------------
#define PAD 36

__device__ __forceinline__ uint32_t f2tf32(float f) {
    uint32_t u;
    asm("cvt.rna.tf32.f32 %0, %1;" : "=r"(u) : "f"(f));
    return u;
}

__device__ __forceinline__ void mma_tf32(float (&d)[4], const uint32_t (&a)[4],
                                         const uint32_t (&b)[2]) {
    asm volatile(
        "mma.sync.aligned.m16n8k8.row.col.f32.tf32.tf32.f32 "
        "{%0,%1,%2,%3}, {%4,%5,%6,%7}, {%8,%9}, {%0,%1,%2,%3};\n"
        : "+f"(d[0]), "+f"(d[1]), "+f"(d[2]), "+f"(d[3])
        : "r"(a[0]), "r"(a[1]), "r"(a[2]), "r"(a[3]), "r"(b[0]), "r"(b[1]));
}

// Mainloop over K=1024. X row-major [*,1024]; W row-major [n][1024].
__device__ __forceinline__ void gemm_tile_tf32(const float* __restrict__ X,
                                               const float* __restrict__ W,
                                               uint32_t* As, uint32_t* Bs,
                                               int m0, int n0,
                                               float (&acc)[4][4][4]) {
    const int tid  = threadIdx.x;
    const int warp = tid >> 5;
    const int lane = tid & 31;
    const int g = lane >> 2;      // group id (rows)
    const int t = lane & 3;       // thread in group (k / cols)
    const int wm = (warp & 1) * 64;
    const int wn = (warp >> 1) * 32;

    // loader mapping: 256 threads cover 32 rows x 8 float4 k-chunks per pass
    const int lrow = tid >> 3;          // 0..31
    const int lck  = (tid & 7) * 4;     // k offset 0..28

    float4 ra[4], rb[4];
#pragma unroll
    for (int r = 0; r < 4; r++) {
        ra[r] = *(const float4*)&X[(size_t)(m0 + lrow + r * 32) * DD + lck];
        rb[r] = *(const float4*)&W[(size_t)(n0 + lrow + r * 32) * DD + lck];
    }

    for (int k0 = 0; k0 < DD; k0 += 32) {
        // convert + store staged tile
#pragma unroll
        for (int r = 0; r < 4; r++) {
            uint32_t* pa = &As[(lrow + r * 32) * PAD + lck];
            pa[0] = f2tf32(ra[r].x); pa[1] = f2tf32(ra[r].y);
            pa[2] = f2tf32(ra[r].z); pa[3] = f2tf32(ra[r].w);
            uint32_t* pb = &Bs[(lrow + r * 32) * PAD + lck];
            pb[0] = f2tf32(rb[r].x); pb[1] = f2tf32(rb[r].y);
            pb[2] = f2tf32(rb[r].z); pb[3] = f2tf32(rb[r].w);
        }
        __syncthreads();

        // prefetch next K tile into registers (hidden under compute)
        if (k0 + 32 < DD) {
#pragma unroll
            for (int r = 0; r < 4; r++) {
                ra[r] = *(const float4*)&X[(size_t)(m0 + lrow + r * 32) * DD + k0 + 32 + lck];
                rb[r] = *(const float4*)&W[(size_t)(n0 + lrow + r * 32) * DD + k0 + 32 + lck];
            }
        }

        // compute: 4 k-steps of 8
#pragma unroll
        for (int ks = 0; ks < 4; ks++) {
            const int kb = ks * 8;
            uint32_t af[4][4], bf[4][2];
#pragma unroll
            for (int mi = 0; mi < 4; mi++) {
                const int r0 = wm + mi * 16 + g;
                af[mi][0] = As[(r0)     * PAD + kb + t];
                af[mi][1] = As[(r0 + 8) * PAD + kb + t];
                af[mi][2] = As[(r0)     * PAD + kb + t + 4];
                af[mi][3] = As[(r0 + 8) * PAD + kb + t + 4];
            }
#pragma unroll
            for (int ni = 0; ni < 4; ni++) {
                const int c0 = wn + ni * 8 + g;
                bf[ni][0] = Bs[c0 * PAD + kb + t];
                bf[ni][1] = Bs[c0 * PAD + kb + t + 4];
            }
#pragma unroll
            for (int mi = 0; mi < 4; mi++)
#pragma unroll
                for (int ni = 0; ni < 4; ni++)
                    mma_tf32(acc[mi][ni], af[mi], bf[ni]);
        }
        __syncthreads();
    }
}

// ---------------------------------------------------------------------------
// Kernel 1: QKV projection (tensor core). grid = (8, 32, 3)
// Output into head layout [B,H,S,HD].
// ---------------------------------------------------------------------------
__global__ __launch_bounds__(256)
void qkv_proj_tc(const float* __restrict__ q_in,
                 const float* __restrict__ k_in,
                 const float* __restrict__ v_in,
                 const float* __restrict__ Wq, const float* __restrict__ bq,
                 const float* __restrict__ Wk, const float* __restrict__ bk,
                 const float* __restrict__ Wv, const float* __restrict__ bv) {
    const int which = blockIdx.z;
    const float* __restrict__ X    = (which == 0) ? q_in : (which == 1) ? k_in : v_in;
    const float* __restrict__ W    = (which == 0) ? Wq   : (which == 1) ? Wk   : Wv;
    const float* __restrict__ bias = (which == 0) ? bq   : (which == 1) ? bk   : bv;
    float* __restrict__ out        = (which == 0) ? g_q  : (which == 1) ? g_k  : g_v;

    __shared__ uint32_t As[128 * PAD];
    __shared__ uint32_t Bs[128 * PAD];

    float acc[4][4][4];
#pragma unroll
    for (int mi = 0; mi < 4; mi++)
#pragma unroll
        for (int ni = 0; ni < 4; ni++)
#pragma unroll
            for (int r = 0; r < 4; r++) acc[mi][ni][r] = 0.f;

    const int m0 = blockIdx.y * 128;
    const int n0 = blockIdx.x * 128;
    gemm_tile_tf32(X, W, As, Bs, m0, n0, acc);

    const int tid  = threadIdx.x;
    const int warp = tid >> 5;
    const int lane = tid & 31;
    const int g = lane >> 2, t = lane & 3;
    const int wm = (warp & 1) * 64;
    const int wn = (warp >> 1) * 32;

#pragma unroll
    for (int mi = 0; mi < 4; mi++) {
#pragma unroll
        for (int rr = 0; rr < 2; rr++) {
            const int m = m0 + wm + mi * 16 + rr * 8 + g;
            const int b = m >> 11;
            const int s = m & 2047;
#pragma unroll
            for (int ni = 0; ni < 4; ni++) {
                const int n = n0 + wn + ni * 8 + t * 2;
                const int h = n >> 6;
                const int d = n & 63;
                float2 v;
                v.x = acc[mi][ni][rr * 2 + 0] + bias[n];
                v.y = acc[mi][ni][rr * 2 + 1] + bias[n + 1];
                *(float2*)&out[((size_t)(b * HH + h) * SS + s) * HD + d] = v;
            }
        }
    }
}

// ---------------------------------------------------------------------------
// Kernel 3: output projection (tensor core). X = g_ctx [M][1024] row-major.
// grid = (8, 32)
// ---------------------------------------------------------------------------
__global__ __launch_bounds__(256)
void out_proj_tc(const float* __restrict__ Wo, const float* __restrict__ bo,
                 float* __restrict__ out) {
    __shared__ uint32_t As[128 * PAD];
    __shared__ uint32_t Bs[128 * PAD];

    float acc[4][4][4];
#pragma unroll
    for (int mi = 0; mi < 4; mi++)
#pragma unroll
        for (int ni = 0; ni < 4; ni++)
#pragma unroll
            for (int r = 0; r < 4; r++) acc[mi][ni][r] = 0.f;

    const int m0 = blockIdx.y * 128;
    const int n0 = blockIdx.x * 128;
    gemm_tile_tf32(g_ctx, Wo, As, Bs, m0, n0, acc);

    const int tid  = threadIdx.x;
    const int warp = tid >> 5;
    const int lane = tid & 31;
    const int g = lane >> 2, t = lane & 3;
    const int wm = (warp & 1) * 64;
    const int wn = (warp >> 1) * 32;

#pragma unroll
    for (int mi = 0; mi < 4; mi++) {
#pragma unroll
        for (int rr = 0; rr < 2; rr++) {
            const int m = m0 + wm + mi * 16 + rr * 8 + g;
#pragma unroll
            for (int ni = 0; ni < 4; ni++) {
                const int n = n0 + wn + ni * 8 + t * 2;
                float2 v;
                v.x = acc[mi][ni][rr * 2 + 0] + bo[n];
                v.y = acc[mi][ni][rr * 2 + 1] + bo[n + 1];
                *(float2*)&out[(size_t)m * DD + n] = v;
            }
        }
    }
}

// ---------------------------------------------------------------------------
// Kernel 2: causal flash attention per (q-tile=64, head, batch). SIMT fp32.
// ---------------------------------------------------------------------------
#define FA_SMEM (4 * 64 * 65 * sizeof(float))

__global__ __launch_bounds__(256, 2)
void flash_attn_kernel() {
    extern __shared__ float smem[];
    float (*Qs)[65] = (float (*)[65])(smem);
    float (*Ks)[65] = (float (*)[65])(smem + 64 * 65);
    float (*Vs)[65] = (float (*)[65])(smem + 2 * 64 * 65);
    float (*Ps)[65] = (float (*)[65])(smem + 3 * 64 * 65);

    const int qt = blockIdx.x;
    const int h  = blockIdx.y;
    const int b  = blockIdx.z;
    const int tid = threadIdx.x;
    const int tx = tid & 15;
    const int ty = tid >> 4;
    const int q0 = qt * 64;

    const float* __restrict__ Qb = g_q + (size_t)(b * HH + h) * SS * HD;
    const float* __restrict__ Kb = g_k + (size_t)(b * HH + h) * SS * HD;
    const float* __restrict__ Vb = g_v + (size_t)(b * HH + h) * SS * HD;

    for (int i = tid; i < 64 * 64; i += 256) {
        const int r = i >> 6, c = i & 63;
        Qs[r][c] = Qb[(size_t)(q0 + r) * HD + c];
    }

    float acc[4][4];
    float mrow[4], lrow[4];
#pragma unroll
    for (int i = 0; i < 4; i++) {
        mrow[i] = -1e30f;
        lrow[i] = 0.f;
#pragma unroll
        for (int j = 0; j < 4; j++) acc[i][j] = 0.f;
    }

    const float scale = 0.125f;
    const int ntiles = qt + 1;

    for (int tt = 0; tt < ntiles; tt++) {
        const int k0 = tt * 64;
        for (int i = tid; i < 64 * 64; i += 256) {
            const int r = i >> 6, c = i & 63;
            Ks[r][c] = Kb[(size_t)(k0 + r) * HD + c];
            Vs[r][c] = Vb[(size_t)(k0 + r) * HD + c];
        }
        __syncthreads();

        float sv[4][4];
#pragma unroll
        for (int i = 0; i < 4; i++)
#pragma unroll
            for (int j = 0; j < 4; j++) sv[i][j] = 0.f;

#pragma unroll 8
        for (int k = 0; k < 64; k++) {
            float a[4], bb[4];
#pragma unroll
            for (int i = 0; i < 4; i++) a[i]  = Qs[ty * 4 + i][k];
#pragma unroll
            for (int j = 0; j < 4; j++) bb[j] = Ks[tx * 4 + j][k];
#pragma unroll
            for (int i = 0; i < 4; i++)
#pragma unroll
                for (int j = 0; j < 4; j++) sv[i][j] = fmaf(a[i], bb[j], sv[i][j]);
        }

#pragma unroll
        for (int i = 0; i < 4; i++) {
            const int qi = q0 + ty * 4 + i;
#pragma unroll
            for (int j = 0; j < 4; j++) {
                const int kj = k0 + tx * 4 + j;
                float x = sv[i][j] * scale;
                if (kj > qi) x -= 1e9f;
                sv[i][j] = x;
            }
        }

        float mt[4];
#pragma unroll
        for (int i = 0; i < 4; i++) {
            float m = fmaxf(fmaxf(sv[i][0], sv[i][1]), fmaxf(sv[i][2], sv[i][3]));
#pragma unroll
            for (int off = 8; off >= 1; off >>= 1)
                m = fmaxf(m, __shfl_xor_sync(0xffffffffu, m, off));
            mt[i] = m;
        }
#pragma unroll
        for (int i = 0; i < 4; i++) {
            const float mnew = fmaxf(mrow[i], mt[i]);
            const float alpha = __expf(mrow[i] - mnew);
            float s = 0.f;
#pragma unroll
            for (int j = 0; j < 4; j++) {
                const float p = __expf(sv[i][j] - mnew);
                sv[i][j] = p;
                s += p;
            }
#pragma unroll
            for (int off = 8; off >= 1; off >>= 1)
                s += __shfl_xor_sync(0xffffffffu, s, off);
            lrow[i] = lrow[i] * alpha + s;
            mrow[i] = mnew;
#pragma unroll
            for (int j = 0; j < 4; j++) acc[i][j] *= alpha;
        }

#pragma unroll
        for (int i = 0; i < 4; i++)
#pragma unroll
            for (int j = 0; j < 4; j++) Ps[ty * 4 + i][tx * 4 + j] = sv[i][j];
        __syncthreads();

#pragma unroll 8
        for (int c = 0; c < 64; c++) {
            float pr[4], vv[4];
#pragma unroll
            for (int i = 0; i < 4; i++) pr[i] = Ps[ty * 4 + i][c];
#pragma unroll
            for (int j = 0; j < 4; j++) vv[j] = Vs[c][tx * 4 + j];
#pragma unroll
            for (int i = 0; i < 4; i++)
#pragma unroll
                for (int j = 0; j < 4; j++) acc[i][j] = fmaf(pr[i], vv[j], acc[i][j]);
        }
        __syncthreads();
    }

    // normalize + store ctx in [B,S,D] layout (GEMM-friendly for out proj)
#pragma unroll
    for (int i = 0; i < 4; i++) {
        const float inv = 1.0f / lrow[i];
        float* orow = g_ctx + ((size_t)(b * SS + q0 + ty * 4 + i)) * DD + h * HD;
#pragma unroll
        for (int j = 0; j < 4; j++) orow[tx * 4 + j] = acc[i][j] * inv;
    }
}

// ---------------------------------------------------------------------------
extern "C" void kernel_launch(void* const* d_in, const int* in_sizes, int n_in,
                              void* d_out, int out_size) {
    const float* query = (const float*)d_in[0];
    const float* key   = (const float*)d_in[1];
    const float* value = (const float*)d_in[2];
    // d_in[3] = mask (causal; applied analytically in-kernel)
    const float* Wq = (const float*)d_in[4];
    const float* bq = (const float*)d_in[5];
    const float* Wk = (const float*)d_in[6];
    const float* bk = (const float*)d_in[7];
    const float* Wv = (const float*)d_in[8];
    const float* bv = (const float*)d_in[9];
    const float* Wo = (const float*)d_in[10];
    const float* bo = (const float*)d_in[11];
    float* out = (float*)d_out;

    cudaFuncSetAttribute(flash_attn_kernel,
                         cudaFuncAttributeMaxDynamicSharedMemorySize, FA_SMEM);

    dim3 gproj(DD / 128, MM / 128, 3);
    qkv_proj_tc<<<gproj, 256>>>(query, key, value, Wq, bq, Wk, bk, Wv, bv);

    dim3 gfa(SS / 64, HH, BB);
    flash_attn_kernel<<<gfa, 256, FA_SMEM>>>();

    dim3 gout(DD / 128, MM / 128);
    out_proj_tc<<<gout, 256>>>(Wo, bo, out);
}

// round 3
// speedup vs baseline: 2.6839x; 1.4740x over previous
#include <cuda_runtime.h>
#include <math.h>
#include <stdint.h>

// Problem constants
#define BB 2
#define SS 2048
#define DD 1024
#define HH 16
#define HD 64
#define MM (BB * SS)   // 4096

// Scratch: Q,K,V in head layout [B,H,S,HD]; CTX in [B,S,D]
__device__ float g_q[BB * HH * SS * HD];
__device__ float g_k[BB * HH * SS * HD];
__device__ float g_v[BB * HH * SS * HD];
__device__ float g_ctx[BB * SS * DD];

// ---------------------------------------------------------------------------
// Common tf32 helpers
// ---------------------------------------------------------------------------
__device__ __forceinline__ uint32_t f2tf32(float f) {
    uint32_t u;
    asm("cvt.rna.tf32.f32 %0, %1;" : "=r"(u) : "f"(f));
    return u;
}

__device__ __forceinline__ void mma_tf32(float (&d)[4], const uint32_t (&a)[4],
                                         const uint32_t (&b)[2]) {
    asm volatile(
        "mma.sync.aligned.m16n8k8.row.col.f32.tf32.tf32.f32 "
        "{%0,%1,%2,%3}, {%4,%5,%6,%7}, {%8,%9}, {%0,%1,%2,%3};\n"
        : "+f"(d[0]), "+f"(d[1]), "+f"(d[2]), "+f"(d[3])
        : "r"(a[0]), "r"(a[1]), "r"(a[2]), "r"(a[3]), "r"(b[0]), "r"(b[1]));
}

// ---------------------------------------------------------------------------
// tf32 GEMM for projections: C[m,n] = sum_k X[m,k] * W[n,k]
// 128x128 block, BK=32, 256 threads.
// ---------------------------------------------------------------------------
#define PAD 36

__device__ __forceinline__ void gemm_tile_tf32(const float* __restrict__ X,
                                               const float* __restrict__ W,
                                               uint32_t* As, uint32_t* Bs,
                                               int m0, int n0,
                                               float (&acc)[4][4][4]) {
    const int tid  = threadIdx.x;
    const int warp = tid >> 5;
    const int lane = tid & 31;
    const int g = lane >> 2;
    const int t = lane & 3;
    const int wm = (warp & 1) * 64;
    const int wn = (warp >> 1) * 32;

    const int lrow = tid >> 3;
    const int lck  = (tid & 7) * 4;

    float4 ra[4], rb[4];
#pragma unroll
    for (int r = 0; r < 4; r++) {
        ra[r] = *(const float4*)&X[(size_t)(m0 + lrow + r * 32) * DD + lck];
        rb[r] = *(const float4*)&W[(size_t)(n0 + lrow + r * 32) * DD + lck];
    }

    for (int k0 = 0; k0 < DD; k0 += 32) {
#pragma unroll
        for (int r = 0; r < 4; r++) {
            uint32_t* pa = &As[(lrow + r * 32) * PAD + lck];
            pa[0] = f2tf32(ra[r].x); pa[1] = f2tf32(ra[r].y);
            pa[2] = f2tf32(ra[r].z); pa[3] = f2tf32(ra[r].w);
            uint32_t* pb = &Bs[(lrow + r * 32) * PAD + lck];
            pb[0] = f2tf32(rb[r].x); pb[1] = f2tf32(rb[r].y);
            pb[2] = f2tf32(rb[r].z); pb[3] = f2tf32(rb[r].w);
        }
        __syncthreads();

        if (k0 + 32 < DD) {
#pragma unroll
            for (int r = 0; r < 4; r++) {
                ra[r] = *(const float4*)&X[(size_t)(m0 + lrow + r * 32) * DD + k0 + 32 + lck];
                rb[r] = *(const float4*)&W[(size_t)(n0 + lrow + r * 32) * DD + k0 + 32 + lck];
            }
        }

#pragma unroll
        for (int ks = 0; ks < 4; ks++) {
            const int kb = ks * 8;
            uint32_t af[4][4], bf[4][2];
#pragma unroll
            for (int mi = 0; mi < 4; mi++) {
                const int r0 = wm + mi * 16 + g;
                af[mi][0] = As[(r0)     * PAD + kb + t];
                af[mi][1] = As[(r0 + 8) * PAD + kb + t];
                af[mi][2] = As[(r0)     * PAD + kb + t + 4];
                af[mi][3] = As[(r0 + 8) * PAD + kb + t + 4];
            }
#pragma unroll
            for (int ni = 0; ni < 4; ni++) {
                const int c0 = wn + ni * 8 + g;
                bf[ni][0] = Bs[c0 * PAD + kb + t];
                bf[ni][1] = Bs[c0 * PAD + kb + t + 4];
            }
#pragma unroll
            for (int mi = 0; mi < 4; mi++)
#pragma unroll
                for (int ni = 0; ni < 4; ni++)
                    mma_tf32(acc[mi][ni], af[mi], bf[ni]);
        }
        __syncthreads();
    }
}

// ---------------------------------------------------------------------------
// Kernel 1: QKV projection (tensor core). grid = (8, 32, 3)
// ---------------------------------------------------------------------------
__global__ __launch_bounds__(256)
void qkv_proj_tc(const float* __restrict__ q_in,
                 const float* __restrict__ k_in,
                 const float* __restrict__ v_in,
                 const float* __restrict__ Wq, const float* __restrict__ bq,
                 const float* __restrict__ Wk, const float* __restrict__ bk,
                 const float* __restrict__ Wv, const float* __restrict__ bv) {
    const int which = blockIdx.z;
    const float* __restrict__ X    = (which == 0) ? q_in : (which == 1) ? k_in : v_in;
    const float* __restrict__ W    = (which == 0) ? Wq   : (which == 1) ? Wk   : Wv;
    const float* __restrict__ bias = (which == 0) ? bq   : (which == 1) ? bk   : bv;
    float* __restrict__ out        = (which == 0) ? g_q  : (which == 1) ? g_k  : g_v;

    __shared__ uint32_t As[128 * PAD];
    __shared__ uint32_t Bs[128 * PAD];

    float acc[4][4][4];
#pragma unroll
    for (int mi = 0; mi < 4; mi++)
#pragma unroll
        for (int ni = 0; ni < 4; ni++)
#pragma unroll
            for (int r = 0; r < 4; r++) acc[mi][ni][r] = 0.f;

    const int m0 = blockIdx.y * 128;
    const int n0 = blockIdx.x * 128;
    gemm_tile_tf32(X, W, As, Bs, m0, n0, acc);

    const int tid  = threadIdx.x;
    const int warp = tid >> 5;
    const int lane = tid & 31;
    const int g = lane >> 2, t = lane & 3;
    const int wm = (warp & 1) * 64;
    const int wn = (warp >> 1) * 32;

#pragma unroll
    for (int mi = 0; mi < 4; mi++) {
#pragma unroll
        for (int rr = 0; rr < 2; rr++) {
            const int m = m0 + wm + mi * 16 + rr * 8 + g;
            const int b = m >> 11;
            const int s = m & 2047;
#pragma unroll
            for (int ni = 0; ni < 4; ni++) {
                const int n = n0 + wn + ni * 8 + t * 2;
                const int h = n >> 6;
                const int d = n & 63;
                float2 v;
                v.x = acc[mi][ni][rr * 2 + 0] + bias[n];
                v.y = acc[mi][ni][rr * 2 + 1] + bias[n + 1];
                *(float2*)&out[((size_t)(b * HH + h) * SS + s) * HD + d] = v;
            }
        }
    }
}

// ---------------------------------------------------------------------------
// Kernel 3: output projection (tensor core). grid = (8, 32)
// ---------------------------------------------------------------------------
__global__ __launch_bounds__(256)
void out_proj_tc(const float* __restrict__ Wo, const float* __restrict__ bo,
                 float* __restrict__ out) {
    __shared__ uint32_t As[128 * PAD];
    __shared__ uint32_t Bs[128 * PAD];

    float acc[4][4][4];
#pragma unroll
    for (int mi = 0; mi < 4; mi++)
#pragma unroll
        for (int ni = 0; ni < 4; ni++)
#pragma unroll
            for (int r = 0; r < 4; r++) acc[mi][ni][r] = 0.f;

    const int m0 = blockIdx.y * 128;
    const int n0 = blockIdx.x * 128;
    gemm_tile_tf32(g_ctx, Wo, As, Bs, m0, n0, acc);

    const int tid  = threadIdx.x;
    const int warp = tid >> 5;
    const int lane = tid & 31;
    const int g = lane >> 2, t = lane & 3;
    const int wm = (warp & 1) * 64;
    const int wn = (warp >> 1) * 32;

#pragma unroll
    for (int mi = 0; mi < 4; mi++) {
#pragma unroll
        for (int rr = 0; rr < 2; rr++) {
            const int m = m0 + wm + mi * 16 + rr * 8 + g;
#pragma unroll
            for (int ni = 0; ni < 4; ni++) {
                const int n = n0 + wn + ni * 8 + t * 2;
                float2 v;
                v.x = acc[mi][ni][rr * 2 + 0] + bo[n];
                v.y = acc[mi][ni][rr * 2 + 1] + bo[n + 1];
                *(float2*)&out[(size_t)m * DD + n] = v;
            }
        }
    }
}

// ---------------------------------------------------------------------------
// Kernel 2: tensor-core causal flash attention.
// CTA: 128 q-rows x (head, batch); 8 warps x m16; KV tiles of 64.
// QK^T in split-tf32 (3 MMAs, ~fp32 accuracy); PV in plain tf32.
// ---------------------------------------------------------------------------
#define QPAD 68
#define VPAD 72
#define FA_QS_OFF 0
#define FA_KS_OFF (128 * QPAD)                    // floats
#define FA_VS_OFF (FA_KS_OFF + 64 * QPAD)
#define FA_PS_OFF (FA_VS_OFF + 64 * VPAD)
#define FA_WORDS  (FA_PS_OFF + 128 * QPAD)
#define FA_SMEM   (FA_WORDS * 4)

__global__ __launch_bounds__(256, 2)
void flash_attn_tc() {
    extern __shared__ float smem[];
    float*    Qs = smem + FA_QS_OFF;   // [128][QPAD] raw fp32
    float*    Ks = smem + FA_KS_OFF;   // [64][QPAD]  raw fp32
    float*    Vs = smem + FA_VS_OFF;   // [64][VPAD]  raw fp32
    uint32_t* Ps = (uint32_t*)(smem + FA_PS_OFF);  // [128][QPAD] tf32 bits

    const int qt = (gridDim.x - 1) - blockIdx.x;   // heavy tiles first
    const int h  = blockIdx.y;
    const int b  = blockIdx.z;
    const int tid  = threadIdx.x;
    const int warp = tid >> 5;
    const int lane = tid & 31;
    const int g = lane >> 2;
    const int t = lane & 3;
    const int wm = warp * 16;          // warp's q-row base within tile
    const int q0 = qt * 128;

    const float* __restrict__ Qb = g_q + (size_t)(b * HH + h) * SS * HD;
    const float* __restrict__ Kb = g_k + (size_t)(b * HH + h) * SS * HD;
    const float* __restrict__ Vb = g_v + (size_t)(b * HH + h) * SS * HD;

    // load Q tile: 128 rows x 16 float4
    {
        const int lr = tid >> 4;            // 0..15
        const int lc = (tid & 15) * 4;      // 0..60
#pragma unroll
        for (int r = 0; r < 8; r++) {
            float4 v = *(const float4*)&Qb[(size_t)(q0 + lr + r * 16) * HD + lc];
            float* p = &Qs[(lr + r * 16) * QPAD + lc];
            p[0] = v.x; p[1] = v.y; p[2] = v.z; p[3] = v.w;
        }
    }

    float oacc[8][4];
#pragma unroll
    for (int ni = 0; ni < 8; ni++)
#pragma unroll
        for (int r = 0; r < 4; r++) oacc[ni][r] = 0.f;
    float m0r = -1e30f, m1r = -1e30f, l0r = 0.f, l1r = 0.f;

    const float scale = 0.125f;
    const int ntiles = 2 * qt + 2;

    for (int tt = 0; tt < ntiles; tt++) {
        const int k0 = tt * 64;
        // load K,V tile: 64 rows x 16 float4 each
        {
            const int lr = tid >> 4;
            const int lc = (tid & 15) * 4;
#pragma unroll
            for (int r = 0; r < 4; r++) {
                float4 kv = *(const float4*)&Kb[(size_t)(k0 + lr + r * 16) * HD + lc];
                float* p = &Ks[(lr + r * 16) * QPAD + lc];
                p[0] = kv.x; p[1] = kv.y; p[2] = kv.z; p[3] = kv.w;
                float4 vv = *(const float4*)&Vb[(size_t)(k0 + lr + r * 16) * HD + lc];
                float* q = &Vs[(lr + r * 16) * VPAD + lc];
                q[0] = vv.x; q[1] = vv.y; q[2] = vv.z; q[3] = vv.w;
            }
        }
        __syncthreads();

        // S = Q K^T via split-tf32
        float sacc[8][4];
#pragma unroll
        for (int ni = 0; ni < 8; ni++)
#pragma unroll
            for (int r = 0; r < 4; r++) sacc[ni][r] = 0.f;

#pragma unroll
        for (int ks = 0; ks < 8; ks++) {
            const int kb = ks * 8;
            float qraw[4];
            qraw[0] = Qs[(wm + g)     * QPAD + kb + t];
            qraw[1] = Qs[(wm + g + 8) * QPAD + kb + t];
            qraw[2] = Qs[(wm + g)     * QPAD + kb + t + 4];
            qraw[3] = Qs[(wm + g + 8) * QPAD + kb + t + 4];
            uint32_t ahi[4], alo[4];
#pragma unroll
            for (int r = 0; r < 4; r++) {
                ahi[r] = f2tf32(qraw[r]);
                alo[r] = f2tf32(qraw[r] - __uint_as_float(ahi[r]));
            }
#pragma unroll
            for (int ni = 0; ni < 8; ni++) {
                float b0 = Ks[(ni * 8 + g) * QPAD + kb + t];
                float b1 = Ks[(ni * 8 + g) * QPAD + kb + t + 4];
                uint32_t bhi[2], blo[2];
                bhi[0] = f2tf32(b0); blo[0] = f2tf32(b0 - __uint_as_float(bhi[0]));
                bhi[1] = f2tf32(b1); blo[1] = f2tf32(b1 - __uint_as_float(bhi[1]));
                mma_tf32(sacc[ni], ahi, bhi);
                mma_tf32(sacc[ni], ahi, blo);
                mma_tf32(sacc[ni], alo, bhi);
            }
        }

        // scale + causal mask (only last 2 tiles touch the diagonal)
        const bool need_mask = (tt >= ntiles - 2);
        const int qi0 = q0 + wm + g;
        const int qi1 = qi0 + 8;
#pragma unroll
        for (int ni = 0; ni < 8; ni++) {
            const int c0 = k0 + ni * 8 + 2 * t;
            sacc[ni][0] *= scale; sacc[ni][1] *= scale;
            sacc[ni][2] *= scale; sacc[ni][3] *= scale;
            if (need_mask) {
                if (c0 > qi0)     sacc[ni][0] -= 1e9f;
                if (c0 + 1 > qi0) sacc[ni][1] -= 1e9f;
                if (c0 > qi1)     sacc[ni][2] -= 1e9f;
                if (c0 + 1 > qi1) sacc[ni][3] -= 1e9f;
            }
        }

        // online softmax (rows g, g+8); row spread over 4 lanes (shfl 1,2)
        float mx0 = -1e30f, mx1 = -1e30f;
#pragma unroll
        for (int ni = 0; ni < 8; ni++) {
            mx0 = fmaxf(mx0, fmaxf(sacc[ni][0], sacc[ni][1]));
            mx1 = fmaxf(mx1, fmaxf(sacc[ni][2], sacc[ni][3]));
        }
        mx0 = fmaxf(mx0, __shfl_xor_sync(0xffffffffu, mx0, 1));
        mx0 = fmaxf(mx0, __shfl_xor_sync(0xffffffffu, mx0, 2));
        mx1 = fmaxf(mx1, __shfl_xor_sync(0xffffffffu, mx1, 1));
        mx1 = fmaxf(mx1, __shfl_xor_sync(0xffffffffu, mx1, 2));

        const float mn0 = fmaxf(m0r, mx0);
        const float mn1 = fmaxf(m1r, mx1);
        const float al0 = __expf(m0r - mn0);
        const float al1 = __expf(m1r - mn1);
        float s0 = 0.f, s1 = 0.f;
#pragma unroll
        for (int ni = 0; ni < 8; ni++) {
            float p0 = __expf(sacc[ni][0] - mn0);
            float p1 = __expf(sacc[ni][1] - mn0);
            float p2 = __expf(sacc[ni][2] - mn1);
            float p3 = __expf(sacc[ni][3] - mn1);
            s0 += p0 + p1; s1 += p2 + p3;
            // stage P as tf32 bits
            uint32_t* pr0 = &Ps[(wm + g)     * QPAD + ni * 8 + 2 * t];
            uint32_t* pr1 = &Ps[(wm + g + 8) * QPAD + ni * 8 + 2 * t];
            pr0[0] = f2tf32(p0); pr0[1] = f2tf32(p1);
            pr1[0] = f2tf32(p2); pr1[1] = f2tf32(p3);
        }
        s0 += __shfl_xor_sync(0xffffffffu, s0, 1);
        s0 += __shfl_xor_sync(0xffffffffu, s0, 2);
        s1 += __shfl_xor_sync(0xffffffffu, s1, 1);
        s1 += __shfl_xor_sync(0xffffffffu, s1, 2);
        l0r = l0r * al0 + s0;
        l1r = l1r * al1 + s1;
        m0r = mn0; m1r = mn1;
#pragma unroll
        for (int ni = 0; ni < 8; ni++) {
            oacc[ni][0] *= al0; oacc[ni][1] *= al0;
            oacc[ni][2] *= al1; oacc[ni][3] *= al1;
        }
        __syncwarp();   // P written by this warp, read by this warp

        // O += P @ V  (plain tf32)
#pragma unroll
        for (int ks = 0; ks < 8; ks++) {
            const int kb = ks * 8;
            uint32_t a[4];
            a[0] = Ps[(wm + g)     * QPAD + kb + t];
            a[1] = Ps[(wm + g + 8) * QPAD + kb + t];
            a[2] = Ps[(wm + g)     * QPAD + kb + t + 4];
            a[3] = Ps[(wm + g + 8) * QPAD + kb + t + 4];
#pragma unroll
            for (int ni = 0; ni < 8; ni++) {
                uint32_t bf[2];
                bf[0] = f2tf32(Vs[(kb + t)     * VPAD + ni * 8 + g]);
                bf[1] = f2tf32(Vs[(kb + t + 4) * VPAD + ni * 8 + g]);
                mma_tf32(oacc[ni], a, bf);
            }
        }
        __syncthreads();   // protect K/V/Q smem before next tile load
    }

    // normalize + store ctx in [B,S,D]
    const float inv0 = 1.0f / l0r;
    const float inv1 = 1.0f / l1r;
    const int r0 = q0 + wm + g;
    float* out0 = g_ctx + ((size_t)(b * SS + r0))     * DD + h * HD;
    float* out1 = g_ctx + ((size_t)(b * SS + r0 + 8)) * DD + h * HD;
#pragma unroll
    for (int ni = 0; ni < 8; ni++) {
        const int c = ni * 8 + 2 * t;
        float2 v0, v1;
        v0.x = oacc[ni][0] * inv0; v0.y = oacc[ni][1] * inv0;
        v1.x = oacc[ni][2] * inv1; v1.y = oacc[ni][3] * inv1;
        *(float2*)&out0[c] = v0;
        *(float2*)&out1[c] = v1;
    }
}

// ---------------------------------------------------------------------------
extern "C" void kernel_launch(void* const* d_in, const int* in_sizes, int n_in,
                              void* d_out, int out_size) {
    const float* query = (const float*)d_in[0];
    const float* key   = (const float*)d_in[1];
    const float* value = (const float*)d_in[2];
    // d_in[3] = mask (causal; applied analytically in-kernel)
    const float* Wq = (const float*)d_in[4];
    const float* bq = (const float*)d_in[5];
    const float* Wk = (const float*)d_in[6];
    const float* bk = (const float*)d_in[7];
    const float* Wv = (const float*)d_in[8];
    const float* bv = (const float*)d_in[9];
    const float* Wo = (const float*)d_in[10];
    const float* bo = (const float*)d_in[11];
    float* out = (float*)d_out;

    cudaFuncSetAttribute(flash_attn_tc,
                         cudaFuncAttributeMaxDynamicSharedMemorySize, FA_SMEM);

    dim3 gproj(DD / 128, MM / 128, 3);
    qkv_proj_tc<<<gproj, 256>>>(query, key, value, Wq, bq, Wk, bk, Wv, bv);

    dim3 gfa(SS / 128, HH, BB);
    flash_attn_tc<<<gfa, 256, FA_SMEM>>>();

    dim3 gout(DD / 128, MM / 128);
    out_proj_tc<<<gout, 256>>>(Wo, bo, out);
}

// round 4
// speedup vs baseline: 2.7708x; 1.0324x over previous
#include <cuda_runtime.h>
#include <math.h>
#include <stdint.h>

// Problem constants
#define BB 2
#define SS 2048
#define DD 1024
#define HH 16
#define HD 64
#define MM (BB * SS)   // 4096

// Scratch
__device__ __align__(16) float    g_q[BB * HH * SS * HD];
__device__ __align__(16) float    g_k[BB * HH * SS * HD];
__device__ __align__(16) float    g_v[BB * HH * SS * HD];
__device__ __align__(16) uint32_t g_ctx[BB * SS * DD];     // tf32 bits
__device__ __align__(16) uint32_t g_tq[MM * DD];           // tf32 inputs
__device__ __align__(16) uint32_t g_tk[MM * DD];
__device__ __align__(16) uint32_t g_tv[MM * DD];
__device__ __align__(16) uint32_t g_wq[DD * DD];           // tf32 weights
__device__ __align__(16) uint32_t g_wk[DD * DD];
__device__ __align__(16) uint32_t g_wv[DD * DD];
__device__ __align__(16) uint32_t g_wo[DD * DD];

// ---------------------------------------------------------------------------
// helpers
// ---------------------------------------------------------------------------
__device__ __forceinline__ uint32_t f2tf32(float f) {
    uint32_t u;
    asm("cvt.rna.tf32.f32 %0, %1;" : "=r"(u) : "f"(f));
    return u;
}

__device__ __forceinline__ void mma_tf32(float (&d)[4], const uint32_t (&a)[4],
                                         const uint32_t (&b)[2]) {
    asm volatile(
        "mma.sync.aligned.m16n8k8.row.col.f32.tf32.tf32.f32 "
        "{%0,%1,%2,%3}, {%4,%5,%6,%7}, {%8,%9}, {%0,%1,%2,%3};\n"
        : "+f"(d[0]), "+f"(d[1]), "+f"(d[2]), "+f"(d[3])
        : "r"(a[0]), "r"(a[1]), "r"(a[2]), "r"(a[3]), "r"(b[0]), "r"(b[1]));
}

__device__ __forceinline__ void cp_async16(void* sm, const void* g) {
    uint32_t a = (uint32_t)__cvta_generic_to_shared(sm);
    asm volatile("cp.async.cg.shared.global [%0], [%1], 16;\n" :: "r"(a), "l"(g));
}
__device__ __forceinline__ void cp_commit() {
    asm volatile("cp.async.commit_group;\n");
}

// ---------------------------------------------------------------------------
// Kernel 0: convert inputs + weights to tf32 bits (RNA).
// grid = (1024, 7), 256 threads, grid-stride.
// ---------------------------------------------------------------------------
__global__ __launch_bounds__(256)
void cvt_tf32_all(const float* __restrict__ q, const float* __restrict__ k,
                  const float* __restrict__ v,
                  const float* __restrict__ wq, const float* __restrict__ wk,
                  const float* __restrict__ wv, const float* __restrict__ wo) {
    const int y = blockIdx.y;
    const float* src;
    uint32_t* dst;
    int n4;
    switch (y) {
        case 0: src = q;  dst = g_tq; n4 = MM * DD / 4; break;
        case 1: src = k;  dst = g_tk; n4 = MM * DD / 4; break;
        case 2: src = v;  dst = g_tv; n4 = MM * DD / 4; break;
        case 3: src = wq; dst = g_wq; n4 = DD * DD / 4; break;
        case 4: src = wk; dst = g_wk; n4 = DD * DD / 4; break;
        case 5: src = wv; dst = g_wv; n4 = DD * DD / 4; break;
        default: src = wo; dst = g_wo; n4 = DD * DD / 4; break;
    }
    for (int i = blockIdx.x * blockDim.x + threadIdx.x; i < n4;
         i += gridDim.x * blockDim.x) {
        float4 f = ((const float4*)src)[i];
        uint4 u;
        u.x = f2tf32(f.x); u.y = f2tf32(f.y);
        u.z = f2tf32(f.z); u.w = f2tf32(f.w);
        ((uint4*)dst)[i] = u;
    }
}

// ---------------------------------------------------------------------------
// tf32 GEMM core (operands already tf32 bits): C[m,n] = sum_k X[m,k]*W[n,k]
// 128x128 block, BK=32, 256 threads, cp.async double-buffered.
// ---------------------------------------------------------------------------
#define PAD 36
#define PJ_SMEM (4 * 128 * PAD * 4)   // As[2]+Bs[2]

__device__ __forceinline__ void gemm_issue(uint32_t* As, uint32_t* Bs,
                                           const uint32_t* __restrict__ X,
                                           const uint32_t* __restrict__ W,
                                           int m0, int n0, int k0,
                                           int lr, int lj) {
#pragma unroll
    for (int r = 0; r < 4; r++) {
        cp_async16(&As[(lr + r * 32) * PAD + lj],
                   &X[(size_t)(m0 + lr + r * 32) * DD + k0 + lj]);
        cp_async16(&Bs[(lr + r * 32) * PAD + lj],
                   &W[(size_t)(n0 + lr + r * 32) * DD + k0 + lj]);
    }
    cp_commit();
}

__device__ __forceinline__ void gemm_tile(const uint32_t* __restrict__ X,
                                          const uint32_t* __restrict__ W,
                                          uint32_t* sm, int m0, int n0,
                                          float (&acc)[4][4][4]) {
    uint32_t* As0 = sm;
    uint32_t* As1 = sm + 128 * PAD;
    uint32_t* Bs0 = sm + 2 * 128 * PAD;
    uint32_t* Bs1 = sm + 3 * 128 * PAD;

    const int tid  = threadIdx.x;
    const int warp = tid >> 5;
    const int lane = tid & 31;
    const int g = lane >> 2;
    const int t = lane & 3;
    const int wm = (warp & 1) * 64;
    const int wn = (warp >> 1) * 32;
    const int lr = tid >> 3;
    const int lj = (tid & 7) * 4;

    gemm_issue(As0, Bs0, X, W, m0, n0, 0, lr, lj);
    gemm_issue(As1, Bs1, X, W, m0, n0, 32, lr, lj);

    int s = 0;
    for (int k0 = 0; k0 < DD; k0 += 32, s ^= 1) {
        if (k0 + 32 < DD) asm volatile("cp.async.wait_group 1;\n");
        else              asm volatile("cp.async.wait_group 0;\n");
        __syncthreads();

        uint32_t* As = s ? As1 : As0;
        uint32_t* Bs = s ? Bs1 : Bs0;
#pragma unroll
        for (int ks = 0; ks < 4; ks++) {
            const int kb = ks * 8;
            uint32_t af[4][4], bf[4][2];
#pragma unroll
            for (int mi = 0; mi < 4; mi++) {
                const int r0 = wm + mi * 16 + g;
                af[mi][0] = As[(r0)     * PAD + kb + t];
                af[mi][1] = As[(r0 + 8) * PAD + kb + t];
                af[mi][2] = As[(r0)     * PAD + kb + t + 4];
                af[mi][3] = As[(r0 + 8) * PAD + kb + t + 4];
            }
#pragma unroll
            for (int ni = 0; ni < 4; ni++) {
                const int c0 = wn + ni * 8 + g;
                bf[ni][0] = Bs[c0 * PAD + kb + t];
                bf[ni][1] = Bs[c0 * PAD + kb + t + 4];
            }
#pragma unroll
            for (int mi = 0; mi < 4; mi++)
#pragma unroll
                for (int ni = 0; ni < 4; ni++)
                    mma_tf32(acc[mi][ni], af[mi], bf[ni]);
        }
        __syncthreads();
        if (k0 + 64 < DD)
            gemm_issue(s ? As1 : As0, s ? Bs1 : Bs0, X, W, m0, n0, k0 + 64, lr, lj);
    }
}

// ---------------------------------------------------------------------------
// Kernel 1: QKV projection. grid = (8, 32, 3)
// ---------------------------------------------------------------------------
__global__ __launch_bounds__(256)
void qkv_proj_tc(const float* __restrict__ bq, const float* __restrict__ bk,
                 const float* __restrict__ bv) {
    extern __shared__ uint32_t gsm[];
    const int which = blockIdx.z;
    const uint32_t* __restrict__ X    = (which == 0) ? g_tq : (which == 1) ? g_tk : g_tv;
    const uint32_t* __restrict__ W    = (which == 0) ? g_wq : (which == 1) ? g_wk : g_wv;
    const float*    __restrict__ bias = (which == 0) ? bq   : (which == 1) ? bk   : bv;
    float* __restrict__ out           = (which == 0) ? g_q  : (which == 1) ? g_k  : g_v;

    float acc[4][4][4];
#pragma unroll
    for (int mi = 0; mi < 4; mi++)
#pragma unroll
        for (int ni = 0; ni < 4; ni++)
#pragma unroll
            for (int r = 0; r < 4; r++) acc[mi][ni][r] = 0.f;

    const int m0 = blockIdx.y * 128;
    const int n0 = blockIdx.x * 128;
    gemm_tile(X, W, gsm, m0, n0, acc);

    const int tid  = threadIdx.x;
    const int warp = tid >> 5;
    const int lane = tid & 31;
    const int g = lane >> 2, t = lane & 3;
    const int wm = (warp & 1) * 64;
    const int wn = (warp >> 1) * 32;

#pragma unroll
    for (int mi = 0; mi < 4; mi++) {
#pragma unroll
        for (int rr = 0; rr < 2; rr++) {
            const int m = m0 + wm + mi * 16 + rr * 8 + g;
            const int b = m >> 11;
            const int s = m & 2047;
#pragma unroll
            for (int ni = 0; ni < 4; ni++) {
                const int n = n0 + wn + ni * 8 + t * 2;
                const int h = n >> 6;
                const int d = n & 63;
                float2 v;
                v.x = acc[mi][ni][rr * 2 + 0] + bias[n];
                v.y = acc[mi][ni][rr * 2 + 1] + bias[n + 1];
                *(float2*)&out[((size_t)(b * HH + h) * SS + s) * HD + d] = v;
            }
        }
    }
}

// ---------------------------------------------------------------------------
// Kernel 3: output projection. X = g_ctx (tf32 bits). grid = (8, 32)
// ---------------------------------------------------------------------------
__global__ __launch_bounds__(256)
void out_proj_tc(const float* __restrict__ bo, float* __restrict__ out) {
    extern __shared__ uint32_t gsm[];
    float acc[4][4][4];
#pragma unroll
    for (int mi = 0; mi < 4; mi++)
#pragma unroll
        for (int ni = 0; ni < 4; ni++)
#pragma unroll
            for (int r = 0; r < 4; r++) acc[mi][ni][r] = 0.f;

    const int m0 = blockIdx.y * 128;
    const int n0 = blockIdx.x * 128;
    gemm_tile(g_ctx, g_wo, gsm, m0, n0, acc);

    const int tid  = threadIdx.x;
    const int warp = tid >> 5;
    const int lane = tid & 31;
    const int g = lane >> 2, t = lane & 3;
    const int wm = (warp & 1) * 64;
    const int wn = (warp >> 1) * 32;

#pragma unroll
    for (int mi = 0; mi < 4; mi++) {
#pragma unroll
        for (int rr = 0; rr < 2; rr++) {
            const int m = m0 + wm + mi * 16 + rr * 8 + g;
#pragma unroll
            for (int ni = 0; ni < 4; ni++) {
                const int n = n0 + wn + ni * 8 + t * 2;
                float2 v;
                v.x = acc[mi][ni][rr * 2 + 0] + bo[n];
                v.y = acc[mi][ni][rr * 2 + 1] + bo[n + 1];
                *(float2*)&out[(size_t)m * DD + n] = v;
            }
        }
    }
}

// ---------------------------------------------------------------------------
// Kernel 2: tensor-core causal flash attention.
// CTA = 128 q-rows x (head, batch), 8 warps x m16, KV tiles of 64.
// K pre-split to (hi,lo) tf32 pairs at load; V pre-converted to tf32.
// Ps aliases Kt (K dead after QK^T); extra barrier protects the alias.
// ---------------------------------------------------------------------------
#define QPAD 68
#define KSTR 136
#define VPAD 72
#define PPAD 68
#define FA_QW (128 * QPAD)                 // 8704 words
#define FA_KW (64 * KSTR)                  // 8704 words (>= 128*PPAD = 8704)
#define FA_VW (64 * VPAD)                  // 4608 words
#define FA_SMEM ((FA_QW + FA_KW + FA_VW) * 4)   // 88064 B

__global__ __launch_bounds__(256, 2)
void flash_attn_tc() {
    extern __shared__ float smem[];
    float*    Qs = smem;                          // [128][QPAD] raw fp32
    uint32_t* Kt = (uint32_t*)(smem + FA_QW);     // [64][KSTR]: (hi,lo) pairs
    uint32_t* Ps = Kt;                            // alias: [128][PPAD] tf32 bits
    uint32_t* Vt = (uint32_t*)(smem + FA_QW + FA_KW);  // [64][VPAD] tf32

    const int qt = (gridDim.x - 1) - blockIdx.x;  // heavy tiles first
    const int h  = blockIdx.y;
    const int b  = blockIdx.z;
    const int tid  = threadIdx.x;
    const int warp = tid >> 5;
    const int lane = tid & 31;
    const int g = lane >> 2;
    const int t = lane & 3;
    const int wm = warp * 16;
    const int q0 = qt * 128;

    const float* __restrict__ Qb = g_q + (size_t)(b * HH + h) * SS * HD;
    const float* __restrict__ Kb = g_k + (size_t)(b * HH + h) * SS * HD;
    const float* __restrict__ Vb = g_v + (size_t)(b * HH + h) * SS * HD;

    // load Q tile (raw fp32)
    {
        const int lr = tid >> 4;
        const int lc = (tid & 15) * 4;
#pragma unroll
        for (int r = 0; r < 8; r++) {
            float4 v = *(const float4*)&Qb[(size_t)(q0 + lr + r * 16) * HD + lc];
            float* p = &Qs[(lr + r * 16) * QPAD + lc];
            p[0] = v.x; p[1] = v.y; p[2] = v.z; p[3] = v.w;
        }
    }

    float oacc[8][4];
#pragma unroll
    for (int ni = 0; ni < 8; ni++)
#pragma unroll
        for (int r = 0; r < 4; r++) oacc[ni][r] = 0.f;
    float m0r = -1e30f, m1r = -1e30f, l0r = 0.f, l1r = 0.f;

    const float scale = 0.125f;
    const int ntiles = 2 * qt + 2;

    for (int tt = 0; tt < ntiles; tt++) {
        const int k0 = tt * 64;
        // load K tile -> (hi,lo) interleaved; V tile -> tf32
        {
            const int lr = tid >> 4;
            const int lc = (tid & 15) * 4;
#pragma unroll
            for (int r = 0; r < 4; r++) {
                const int row = lr + r * 16;
                float4 kv = *(const float4*)&Kb[(size_t)(k0 + row) * HD + lc];
                uint32_t h0 = f2tf32(kv.x), h1 = f2tf32(kv.y);
                uint32_t h2 = f2tf32(kv.z), h3 = f2tf32(kv.w);
                uint4 p0, p1;
                p0.x = h0; p0.y = f2tf32(kv.x - __uint_as_float(h0));
                p0.z = h1; p0.w = f2tf32(kv.y - __uint_as_float(h1));
                p1.x = h2; p1.y = f2tf32(kv.z - __uint_as_float(h2));
                p1.z = h3; p1.w = f2tf32(kv.w - __uint_as_float(h3));
                *(uint4*)&Kt[row * KSTR + 2 * lc]     = p0;
                *(uint4*)&Kt[row * KSTR + 2 * lc + 4] = p1;

                float4 vv = *(const float4*)&Vb[(size_t)(k0 + row) * HD + lc];
                uint4 vt;
                vt.x = f2tf32(vv.x); vt.y = f2tf32(vv.y);
                vt.z = f2tf32(vv.z); vt.w = f2tf32(vv.w);
                *(uint4*)&Vt[row * VPAD + lc] = vt;
            }
        }
        __syncthreads();

        // S = Q K^T via split-tf32
        float sacc[8][4];
#pragma unroll
        for (int ni = 0; ni < 8; ni++)
#pragma unroll
            for (int r = 0; r < 4; r++) sacc[ni][r] = 0.f;

#pragma unroll
        for (int ks = 0; ks < 8; ks++) {
            const int kb = ks * 8;
            float qraw[4];
            qraw[0] = Qs[(wm + g)     * QPAD + kb + t];
            qraw[1] = Qs[(wm + g + 8) * QPAD + kb + t];
            qraw[2] = Qs[(wm + g)     * QPAD + kb + t + 4];
            qraw[3] = Qs[(wm + g + 8) * QPAD + kb + t + 4];
            uint32_t ahi[4], alo[4];
#pragma unroll
            for (int r = 0; r < 4; r++) {
                ahi[r] = f2tf32(qraw[r]);
                alo[r] = f2tf32(qraw[r] - __uint_as_float(ahi[r]));
            }
#pragma unroll
            for (int ni = 0; ni < 8; ni++) {
                const int row = ni * 8 + g;
                uint2 e0 = *(uint2*)&Kt[row * KSTR + 2 * (kb + t)];
                uint2 e1 = *(uint2*)&Kt[row * KSTR + 2 * (kb + t + 4)];
                uint32_t bhi[2] = { e0.x, e1.x };
                uint32_t blo[2] = { e0.y, e1.y };
                mma_tf32(sacc[ni], ahi, bhi);
                mma_tf32(sacc[ni], ahi, blo);
                mma_tf32(sacc[ni], alo, bhi);
            }
        }
        __syncthreads();   // all warps done reading Kt before Ps overwrites it

        // scale + causal mask (only last 2 tiles touch the diagonal)
        const bool need_mask = (tt >= ntiles - 2);
        const int qi0 = q0 + wm + g;
        const int qi1 = qi0 + 8;
#pragma unroll
        for (int ni = 0; ni < 8; ni++) {
            const int c0 = k0 + ni * 8 + 2 * t;
            sacc[ni][0] *= scale; sacc[ni][1] *= scale;
            sacc[ni][2] *= scale; sacc[ni][3] *= scale;
            if (need_mask) {
                if (c0 > qi0)     sacc[ni][0] -= 1e9f;
                if (c0 + 1 > qi0) sacc[ni][1] -= 1e9f;
                if (c0 > qi1)     sacc[ni][2] -= 1e9f;
                if (c0 + 1 > qi1) sacc[ni][3] -= 1e9f;
            }
        }

        // online softmax (rows g, g+8); each row spread over 4 lanes
        float mx0 = -1e30f, mx1 = -1e30f;
#pragma unroll
        for (int ni = 0; ni < 8; ni++) {
            mx0 = fmaxf(mx0, fmaxf(sacc[ni][0], sacc[ni][1]));
            mx1 = fmaxf(mx1, fmaxf(sacc[ni][2], sacc[ni][3]));
        }
        mx0 = fmaxf(mx0, __shfl_xor_sync(0xffffffffu, mx0, 1));
        mx0 = fmaxf(mx0, __shfl_xor_sync(0xffffffffu, mx0, 2));
        mx1 = fmaxf(mx1, __shfl_xor_sync(0xffffffffu, mx1, 1));
        mx1 = fmaxf(mx1, __shfl_xor_sync(0xffffffffu, mx1, 2));

        const float mn0 = fmaxf(m0r, mx0);
        const float mn1 = fmaxf(m1r, mx1);
        const float al0 = __expf(m0r - mn0);
        const float al1 = __expf(m1r - mn1);
        float s0 = 0.f, s1 = 0.f;
#pragma unroll
        for (int ni = 0; ni < 8; ni++) {
            float p0 = __expf(sacc[ni][0] - mn0);
            float p1 = __expf(sacc[ni][1] - mn0);
            float p2 = __expf(sacc[ni][2] - mn1);
            float p3 = __expf(sacc[ni][3] - mn1);
            s0 += p0 + p1; s1 += p2 + p3;
            uint32_t* pr0 = &Ps[(wm + g)     * PPAD + ni * 8 + 2 * t];
            uint32_t* pr1 = &Ps[(wm + g + 8) * PPAD + ni * 8 + 2 * t];
            pr0[0] = f2tf32(p0); pr0[1] = f2tf32(p1);
            pr1[0] = f2tf32(p2); pr1[1] = f2tf32(p3);
        }
        s0 += __shfl_xor_sync(0xffffffffu, s0, 1);
        s0 += __shfl_xor_sync(0xffffffffu, s0, 2);
        s1 += __shfl_xor_sync(0xffffffffu, s1, 1);
        s1 += __shfl_xor_sync(0xffffffffu, s1, 2);
        l0r = l0r * al0 + s0;
        l1r = l1r * al1 + s1;
        m0r = mn0; m1r = mn1;
#pragma unroll
        for (int ni = 0; ni < 8; ni++) {
            oacc[ni][0] *= al0; oacc[ni][1] *= al0;
            oacc[ni][2] *= al1; oacc[ni][3] *= al1;
        }
        __syncwarp();   // P written by this warp, read by this warp

        // O += P @ V (plain tf32, V preconverted)
#pragma unroll
        for (int ks = 0; ks < 8; ks++) {
            const int kb = ks * 8;
            uint32_t a[4];
            a[0] = Ps[(wm + g)     * PPAD + kb + t];
            a[1] = Ps[(wm + g + 8) * PPAD + kb + t];
            a[2] = Ps[(wm + g)     * PPAD + kb + t + 4];
            a[3] = Ps[(wm + g + 8) * PPAD + kb + t + 4];
#pragma unroll
            for (int ni = 0; ni < 8; ni++) {
                uint32_t bf[2];
                bf[0] = Vt[(kb + t)     * VPAD + ni * 8 + g];
                bf[1] = Vt[(kb + t + 4) * VPAD + ni * 8 + g];
                mma_tf32(oacc[ni], a, bf);
            }
        }
        __syncthreads();   // Vt/Ps dead before next tile load
    }

    // normalize + store ctx as tf32 bits in [B,S,D]
    const float inv0 = 1.0f / l0r;
    const float inv1 = 1.0f / l1r;
    const int r0 = q0 + wm + g;
    uint32_t* out0 = g_ctx + ((size_t)(b * SS + r0))     * DD + h * HD;
    uint32_t* out1 = g_ctx + ((size_t)(b * SS + r0 + 8)) * DD + h * HD;
#pragma unroll
    for (int ni = 0; ni < 8; ni++) {
        const int c = ni * 8 + 2 * t;
        uint2 v0, v1;
        v0.x = f2tf32(oacc[ni][0] * inv0); v0.y = f2tf32(oacc[ni][1] * inv0);
        v1.x = f2tf32(oacc[ni][2] * inv1); v1.y = f2tf32(oacc[ni][3] * inv1);
        *(uint2*)&out0[c] = v0;
        *(uint2*)&out1[c] = v1;
    }
}

// ---------------------------------------------------------------------------
extern "C" void kernel_launch(void* const* d_in, const int* in_sizes, int n_in,
                              void* d_out, int out_size) {
    const float* query = (const float*)d_in[0];
    const float* key   = (const float*)d_in[1];
    const float* value = (const float*)d_in[2];
    // d_in[3] = mask (causal; applied analytically in-kernel)
    const float* Wq = (const float*)d_in[4];
    const float* bq = (const float*)d_in[5];
    const float* Wk = (const float*)d_in[6];
    const float* bk = (const float*)d_in[7];
    const float* Wv = (const float*)d_in[8];
    const float* bv = (const float*)d_in[9];
    const float* Wo = (const float*)d_in[10];
    const float* bo = (const float*)d_in[11];
    float* out = (float*)d_out;

    cudaFuncSetAttribute(flash_attn_tc,
                         cudaFuncAttributeMaxDynamicSharedMemorySize, FA_SMEM);
    cudaFuncSetAttribute(qkv_proj_tc,
                         cudaFuncAttributeMaxDynamicSharedMemorySize, PJ_SMEM);
    cudaFuncSetAttribute(out_proj_tc,
                         cudaFuncAttributeMaxDynamicSharedMemorySize, PJ_SMEM);

    dim3 gcvt(1024, 7);
    cvt_tf32_all<<<gcvt, 256>>>(query, key, value, Wq, Wk, Wv, Wo);

    dim3 gproj(DD / 128, MM / 128, 3);
    qkv_proj_tc<<<gproj, 256, PJ_SMEM>>>(bq, bk, bv);

    dim3 gfa(SS / 128, HH, BB);
    flash_attn_tc<<<gfa, 256, FA_SMEM>>>();

    dim3 gout(DD / 128, MM / 128);
    out_proj_tc<<<gout, 256, PJ_SMEM>>>(bo, out);
}